// round 7
// baseline (speedup 1.0000x reference)
#include <cuda_runtime.h>
#include <cuda_bf16.h>

#define DIMN 1024
#define NB 16
#define MATS ((size_t)DIMN * DIMN)     /* 1M  */
#define TOT  ((size_t)NB * MATS)       /* 16M */

// ---------------- scratch (device globals; allocation-free) ----------------
__device__ __nv_bfloat16 g_a1h[TOT],  g_a1l[TOT];
__device__ __nv_bfloat16 g_a2h[TOT],  g_a2l[TOT];
__device__ __nv_bfloat16 g_gwh[MATS], g_gwl[MATS];
__device__ __nv_bfloat16 g_a2ph[TOT], g_a2pl[TOT];
__device__ float         g_S[TOT];
__device__ __nv_bfloat16 g_A1h[TOT],  g_A1l[TOT];     // rowsoftmax(S)
__device__ __nv_bfloat16 g_A2h[TOT],  g_A2l[TOT];     // colsoftmax(S)^T
__device__ __nv_bfloat16 g_a2Th[TOT], g_a2Tl[TOT];    // a2^T
__device__ __nv_bfloat16 g_a1Th[TOT], g_a1Tl[TOT];    // a1^T
__device__ float g_rmax[NB * DIMN], g_rinv[NB * DIMN];
__device__ float g_cmax[NB * DIMN], g_cinv[NB * DIMN];
__device__ float g_rpm[NB * 4 * DIMN], g_rps[NB * 4 * DIMN];  // row partials [z][row][bx(4)]
__device__ float g_cpm[NB * 8 * DIMN], g_cps[NB * 8 * DIMN];  // col partials [z][col][by(8)]

// ---------------- helpers ----------------
__device__ __forceinline__ unsigned smem_u32(const void* p) {
    unsigned r;
    asm("{ .reg .u64 t; cvta.to.shared.u64 t, %1; cvt.u32.u64 %0, t; }"
        : "=r"(r) : "l"(p));
    return r;
}
__device__ __forceinline__ unsigned swz64(unsigned x) {
    return x ^ ((x >> 3) & 0x30);
}
__device__ __forceinline__ void bsplit(float v, __nv_bfloat16& h, __nv_bfloat16& l) {
    h = __float2bfloat16_rn(v);
    l = __float2bfloat16_rn(v - __bfloat162float(h));
}

#define CP16(dst, src) \
    asm volatile("cp.async.cg.shared.global [%0], [%1], 16;" :: "r"(dst), "l"(src))

#define LDSM4(r, addr) \
    asm volatile("ldmatrix.sync.aligned.m8n8.x4.shared.b16 {%0,%1,%2,%3}, [%4];" \
        : "=r"((r)[0]), "=r"((r)[1]), "=r"((r)[2]), "=r"((r)[3]) : "r"(addr))

#define MMA16816(c, a, b)                                                      \
    asm volatile("mma.sync.aligned.m16n8k16.row.col.f32.bf16.bf16.f32 "        \
        "{%0,%1,%2,%3}, {%4,%5,%6,%7}, {%8,%9}, {%0,%1,%2,%3};"                \
        : "+f"((c)[0]), "+f"((c)[1]), "+f"((c)[2]), "+f"((c)[3])               \
        : "r"((a)[0]), "r"((a)[1]), "r"((a)[2]), "r"((a)[3]),                  \
          "r"((b)[0]), "r"((b)[1]))

// ---------------- split-bf16 NT GEMM core ----------------
// CTA tile 128x256, BK=32, 32 K-chunks, 4-stage cp.async, 256 thr,
// 8 warps (2x4), warp tile 64x64. Stage: Ah 8K | Al 8K | Bh 16K | Bl 16K.
#define STAGE_B   49152
#define SMEM_TOT  (4 * STAGE_B)

struct GPtr { const char *ah, *al, *bh, *bl; };

__device__ __forceinline__ void issue_loads(unsigned st, const GPtr& p, unsigned kbyte,
                                            unsigned so0) {
    const unsigned RS = 64u * DIMN * 2u;
    CP16(st +         so0,        p.ah + kbyte);
    CP16(st +         so0 + 4096, p.ah + kbyte + RS);
    CP16(st +  8192 + so0,        p.al + kbyte);
    CP16(st +  8192 + so0 + 4096, p.al + kbyte + RS);
#pragma unroll
    for (unsigned j = 0; j < 4; j++) {
        CP16(st + 16384 + so0 + j * 4096, p.bh + kbyte + j * RS);
        CP16(st + 32768 + so0 + j * 4096, p.bl + kbyte + j * RS);
    }
    asm volatile("cp.async.commit_group;" ::: "memory");
}

__device__ __forceinline__ void mainloop(unsigned sb, const GPtr& p, unsigned so0,
                                         int lane, int wm, int wn,
                                         float (*acc)[8][4])
{
    issue_loads(sb,               p, 0,   so0);
    issue_loads(sb + STAGE_B,     p, 64,  so0);
    issue_loads(sb + 2 * STAGE_B, p, 128, so0);

#pragma unroll 1
    for (int it = 0; it < 32; it++) {
        if (it < 30)       asm volatile("cp.async.wait_group 2;" ::: "memory");
        else if (it == 30) asm volatile("cp.async.wait_group 1;" ::: "memory");
        else               asm volatile("cp.async.wait_group 0;" ::: "memory");
        __syncthreads();
        if (it + 3 < 32) {
            unsigned wst = sb + (unsigned)((it + 3) & 3) * STAGE_B;
            issue_loads(wst, p, (unsigned)(it + 3) * 64, so0);
        }
        const unsigned st = sb + (unsigned)(it & 3) * STAGE_B;

#pragma unroll
        for (int ks = 0; ks < 2; ks++) {
            const unsigned kb = ks * 32;
            unsigned bh[16], bl[16];
#pragma unroll
            for (int nt = 0; nt < 4; nt++) {
                unsigned brow = wn + nt * 16 + (lane & 7) + ((lane >> 4) & 1) * 8;
                unsigned bb   = kb + ((lane >> 3) & 1) * 16;
                unsigned ba   = st + 16384 + swz64(brow * 64 + bb);
                LDSM4(bh + nt * 4, ba);
                LDSM4(bl + nt * 4, ba + 16384);
            }
#pragma unroll
            for (int mf = 0; mf < 4; mf++) {
                unsigned arow = wm + mf * 16 + (lane & 15);
                unsigned ab   = kb + ((lane >> 4) & 1) * 16;
                unsigned aa   = st + swz64(arow * 64 + ab);
                unsigned ah[4], al[4];
                LDSM4(ah, aa);
                LDSM4(al, aa + 8192);
#pragma unroll
                for (int nf = 0; nf < 8; nf++) {
                    MMA16816(acc[mf][nf], ah, bh + nf * 2);
                    MMA16816(acc[mf][nf], ah, bl + nf * 2);
                    MMA16816(acc[mf][nf], al, bh + nf * 2);
                }
            }
        }
    }
}

__device__ __forceinline__ void make_gptr(GPtr& p, unsigned& so0,
    const __nv_bfloat16* Ah, const __nv_bfloat16* Al,
    const __nv_bfloat16* Bh, const __nv_bfloat16* Bl,
    size_t zA, size_t zB, size_t row0, size_t col0, int tid)
{
    size_t ar = row0 + (tid >> 2);
    size_t br = col0 + (tid >> 2);
    size_t ko = (size_t)(tid & 3) * 8;
    p.ah = (const char*)Ah + (zA + ar * DIMN + ko) * 2;
    p.al = (const char*)Al + (zA + ar * DIMN + ko) * 2;
    p.bh = (const char*)Bh + (zB + br * DIMN + ko) * 2;
    p.bl = (const char*)Bl + (zB + br * DIMN + ko) * 2;
    so0 = swz64(((unsigned)(tid >> 2)) * 64 + (tid & 3) * 16);
}

// ---- a2p GEMM: bias add + split bf16 pair out ----
__global__ __launch_bounds__(256, 1)
void gemm_a2p(const __nv_bfloat16* __restrict__ Ah, const __nv_bfloat16* __restrict__ Al,
              const __nv_bfloat16* __restrict__ Bh, const __nv_bfloat16* __restrict__ Bl,
              __nv_bfloat16* __restrict__ outH, __nv_bfloat16* __restrict__ outL,
              const float* __restrict__ bias)
{
    extern __shared__ char smem[];
    const unsigned sb = smem_u32(smem);
    const int tid = threadIdx.x, warp = tid >> 5, lane = tid & 31;
    const int wm = (warp >> 2) * 64, wn = (warp & 3) * 64;
    const size_t row0 = (size_t)blockIdx.y * 128, col0 = (size_t)blockIdx.x * 256;

    GPtr p; unsigned so0;
    make_gptr(p, so0, Ah, Al, Bh, Bl, 0, 0, row0, col0, tid);
    float acc[4][8][4] = {};
    mainloop(sb, p, so0, lane, wm, wn, acc);

    const int g = lane >> 2, t = lane & 3;
#pragma unroll
    for (int mf = 0; mf < 4; mf++)
#pragma unroll
        for (int nf = 0; nf < 8; nf++) {
            const float* c = acc[mf][nf];
            size_t r0 = row0 + wm + mf * 16 + g;
            size_t cc = col0 + wn + nf * 8 + 2 * t;
            float b0 = bias[cc], b1 = bias[cc + 1];
            union { __nv_bfloat16 b[2]; unsigned u; } H0, L0, H1, L1;
            bsplit(c[0] + b0, H0.b[0], L0.b[0]);
            bsplit(c[1] + b1, H0.b[1], L0.b[1]);
            bsplit(c[2] + b0, H1.b[0], L1.b[0]);
            bsplit(c[3] + b1, H1.b[1], L1.b[1]);
            *(unsigned*)(outH + r0 * DIMN + cc)       = H0.u;
            *(unsigned*)(outL + r0 * DIMN + cc)       = L0.u;
            *(unsigned*)(outH + (r0 + 8) * DIMN + cc) = H1.u;
            *(unsigned*)(outL + (r0 + 8) * DIMN + cc) = L1.u;
        }
}

// ---- S GEMM: fp32 out + fused per-CTA row/col softmax partials ----
__global__ __launch_bounds__(256, 1)
void gemm_S(const __nv_bfloat16* __restrict__ Ah, const __nv_bfloat16* __restrict__ Al,
            const __nv_bfloat16* __restrict__ Bh, const __nv_bfloat16* __restrict__ Bl,
            float* __restrict__ outF,
            float* __restrict__ rpm, float* __restrict__ rps,
            float* __restrict__ cpm, float* __restrict__ cps)
{
    extern __shared__ char smem[];
    const unsigned sb = smem_u32(smem);
    const int tid = threadIdx.x, warp = tid >> 5, lane = tid & 31;
    const int wm = (warp >> 2) * 64, wn = (warp & 3) * 64;
    const size_t z = blockIdx.z;
    const size_t row0 = (size_t)blockIdx.y * 128, col0 = (size_t)blockIdx.x * 256;

    GPtr p; unsigned so0;
    make_gptr(p, so0, Ah, Al, Bh, Bl, z * MATS, z * MATS, row0, col0, tid);
    float acc[4][8][4] = {};
    mainloop(sb, p, so0, lane, wm, wn, acc);

    const int g = lane >> 2, t = lane & 3;
    float* outb = outF + z * MATS;
#pragma unroll
    for (int mf = 0; mf < 4; mf++)
#pragma unroll
        for (int nf = 0; nf < 8; nf++) {
            const float* c = acc[mf][nf];
            size_t r0 = row0 + wm + mf * 16 + g;
            size_t cc = col0 + wn + nf * 8 + 2 * t;
            *(float2*)(outb + r0 * DIMN + cc)       = make_float2(c[0], c[1]);
            *(float2*)(outb + (r0 + 8) * DIMN + cc) = make_float2(c[2], c[3]);
        }

    // ---- softmax partials from registers ----
    float rm_[4][2], rs_[4][2];
#pragma unroll
    for (int mf = 0; mf < 4; mf++)
#pragma unroll
        for (int rh = 0; rh < 2; rh++) {
            float m = -1e30f;
#pragma unroll
            for (int nf = 0; nf < 8; nf++)
                m = fmaxf(m, fmaxf(acc[mf][nf][rh * 2], acc[mf][nf][rh * 2 + 1]));
            m = fmaxf(m, __shfl_xor_sync(0xffffffffu, m, 1));
            m = fmaxf(m, __shfl_xor_sync(0xffffffffu, m, 2));
            float s = 0.f;
#pragma unroll
            for (int nf = 0; nf < 8; nf++)
                s += __expf(acc[mf][nf][rh * 2] - m) + __expf(acc[mf][nf][rh * 2 + 1] - m);
            s += __shfl_xor_sync(0xffffffffu, s, 1);
            s += __shfl_xor_sync(0xffffffffu, s, 2);
            rm_[mf][rh] = m; rs_[mf][rh] = s;
        }
    float cm_[8][2], cs_[8][2];
#pragma unroll
    for (int nf = 0; nf < 8; nf++)
#pragma unroll
        for (int cr = 0; cr < 2; cr++) {
            float m = -1e30f;
#pragma unroll
            for (int mf = 0; mf < 4; mf++)
                m = fmaxf(m, fmaxf(acc[mf][nf][cr], acc[mf][nf][2 + cr]));
            m = fmaxf(m, __shfl_xor_sync(0xffffffffu, m, 4));
            m = fmaxf(m, __shfl_xor_sync(0xffffffffu, m, 8));
            m = fmaxf(m, __shfl_xor_sync(0xffffffffu, m, 16));
            float s = 0.f;
#pragma unroll
            for (int mf = 0; mf < 4; mf++)
                s += __expf(acc[mf][nf][cr] - m) + __expf(acc[mf][nf][2 + cr] - m);
            s += __shfl_xor_sync(0xffffffffu, s, 4);
            s += __shfl_xor_sync(0xffffffffu, s, 8);
            s += __shfl_xor_sync(0xffffffffu, s, 16);
            cm_[nf][cr] = m; cs_[nf][cr] = s;
        }

    __syncthreads();   // stage buffers dead; reuse smem for staging
    float* sRM = (float*)smem;        // [4][128]
    float* sRS = sRM + 512;
    float* sCM = sRS + 512;           // [2][256]
    float* sCS = sCM + 512;
    if (t == 0) {
#pragma unroll
        for (int mf = 0; mf < 4; mf++)
#pragma unroll
            for (int rh = 0; rh < 2; rh++) {
                int r = wm + mf * 16 + g + 8 * rh;
                sRM[(warp & 3) * 128 + r] = rm_[mf][rh];
                sRS[(warp & 3) * 128 + r] = rs_[mf][rh];
            }
    }
    if (g == 0) {
#pragma unroll
        for (int nf = 0; nf < 8; nf++)
#pragma unroll
            for (int cr = 0; cr < 2; cr++) {
                int c = wn + nf * 8 + 2 * t + cr;
                sCM[(warp >> 2) * 256 + c] = cm_[nf][cr];
                sCS[(warp >> 2) * 256 + c] = cs_[nf][cr];
            }
    }
    __syncthreads();
    if (tid < 128) {
        int r = tid;
        float m = -1e30f;
#pragma unroll
        for (int w = 0; w < 4; w++) m = fmaxf(m, sRM[w * 128 + r]);
        float s = 0.f;
#pragma unroll
        for (int w = 0; w < 4; w++) s += sRS[w * 128 + r] * __expf(sRM[w * 128 + r] - m);
        size_t ri = (z * DIMN + row0 + r) * 4 + blockIdx.x;
        rpm[ri] = m; rps[ri] = s;
    }
    {
        int c = tid;
        float mc = fmaxf(sCM[c], sCM[256 + c]);
        float sc = sCS[c] * __expf(sCM[c] - mc) + sCS[256 + c] * __expf(sCM[256 + c] - mc);
        size_t ci = (z * DIMN + col0 + c) * 8 + blockIdx.y;
        cpm[ci] = mc; cps[ci] = sc;
    }
}

// ---- merged M1/M2 GEMM: grid z in [0,32), sel = z>>4 ----
__global__ __launch_bounds__(256, 1)
void gemm_dual(const __nv_bfloat16* __restrict__ A1h, const __nv_bfloat16* __restrict__ A1l,
               const __nv_bfloat16* __restrict__ B1h, const __nv_bfloat16* __restrict__ B1l,
               float* __restrict__ o1,
               const __nv_bfloat16* __restrict__ A2h, const __nv_bfloat16* __restrict__ A2l,
               const __nv_bfloat16* __restrict__ B2h, const __nv_bfloat16* __restrict__ B2l,
               float* __restrict__ o2)
{
    extern __shared__ char smem[];
    const unsigned sb = smem_u32(smem);
    const int tid = threadIdx.x, warp = tid >> 5, lane = tid & 31;
    const int wm = (warp >> 2) * 64, wn = (warp & 3) * 64;
    const int sel = blockIdx.z >> 4;
    const size_t z = blockIdx.z & 15;
    const size_t row0 = (size_t)blockIdx.y * 128, col0 = (size_t)blockIdx.x * 256;

    const __nv_bfloat16* Ah = sel ? A2h : A1h;
    const __nv_bfloat16* Al = sel ? A2l : A1l;
    const __nv_bfloat16* Bh = sel ? B2h : B1h;
    const __nv_bfloat16* Bl = sel ? B2l : B1l;
    float* outF = sel ? o2 : o1;

    GPtr p; unsigned so0;
    make_gptr(p, so0, Ah, Al, Bh, Bl, z * MATS, z * MATS, row0, col0, tid);
    float acc[4][8][4] = {};
    mainloop(sb, p, so0, lane, wm, wn, acc);

    const int g = lane >> 2, t = lane & 3;
    float* outb = outF + z * MATS;
#pragma unroll
    for (int mf = 0; mf < 4; mf++)
#pragma unroll
        for (int nf = 0; nf < 8; nf++) {
            const float* c = acc[mf][nf];
            size_t r0 = row0 + wm + mf * 16 + g;
            size_t cc = col0 + wn + nf * 8 + 2 * t;
            *(float2*)(outb + r0 * DIMN + cc)       = make_float2(c[0], c[1]);
            *(float2*)(outb + (r0 + 8) * DIMN + cc) = make_float2(c[2], c[3]);
        }
}

// ---------------- elementwise ----------------
__global__ __launch_bounds__(256)
void split_kernel(const float* __restrict__ in, __nv_bfloat16* __restrict__ h,
                  __nv_bfloat16* __restrict__ l)
{
    size_t i = (size_t)blockIdx.x * 256 + threadIdx.x;
    float4 v = ((const float4*)in)[i];
    union { __nv_bfloat16 b[4]; uint2 u; } H, L;
    bsplit(v.x, H.b[0], L.b[0]); bsplit(v.y, H.b[1], L.b[1]);
    bsplit(v.z, H.b[2], L.b[2]); bsplit(v.w, H.b[3], L.b[3]);
    ((uint2*)h)[i] = H.u;
    ((uint2*)l)[i] = L.u;
}

// fused: row-major split AND transposed split in one read of the input
__global__ __launch_bounds__(256)
void fsplit_kernel(const float* __restrict__ in,
                   __nv_bfloat16* __restrict__ h,  __nv_bfloat16* __restrict__ l,
                   __nv_bfloat16* __restrict__ th, __nv_bfloat16* __restrict__ tl_)
{
    __shared__ float tle[32][33];
    const int z = blockIdx.z;
    const float* src = in + (size_t)z * MATS;
    const int bx = blockIdx.x * 32, by = blockIdx.y * 32;
    const int x = threadIdx.x, y = threadIdx.y;   // block (32, 8)
#pragma unroll
    for (int i = 0; i < 4; i++) {
        int row = by + y + 8 * i;
        float v = src[(size_t)row * DIMN + bx + x];
        tle[y + 8 * i][x] = v;
        __nv_bfloat16 hh, ll;
        bsplit(v, hh, ll);
        size_t o = (size_t)z * MATS + (size_t)row * DIMN + bx + x;
        h[o] = hh; l[o] = ll;
    }
    __syncthreads();
#pragma unroll
    for (int i = 0; i < 4; i++) {
        int cI = bx + y + 8 * i;
        float v = tle[x][y + 8 * i];
        __nv_bfloat16 hh, ll;
        bsplit(v, hh, ll);
        size_t o = (size_t)z * MATS + (size_t)cI * DIMN + by + x;
        th[o] = hh; tl_[o] = ll;
    }
}

// combine COUNT (max,sum) partials -> (max, 1/sum)
template <int COUNT>
__global__ __launch_bounds__(256)
void combine_kernel(const float* __restrict__ pm, const float* __restrict__ ps,
                    float* __restrict__ omax, float* __restrict__ oinv)
{
    int idx = blockIdx.x * 256 + threadIdx.x;   // 16384
    const float* m8 = pm + (size_t)idx * COUNT;
    const float* s8 = ps + (size_t)idx * COUNT;
    float m = -1e30f;
#pragma unroll
    for (int j = 0; j < COUNT; j++) m = fmaxf(m, m8[j]);
    float s = 0.f;
#pragma unroll
    for (int j = 0; j < COUNT; j++) s += s8[j] * __expf(m8[j] - m);
    omax[idx] = m;
    oinv[idx] = 1.0f / s;
}

// fused: A1 = rowsoftmax(S) split (row-major) AND A2T = colsoftmax(S)^T split
__global__ __launch_bounds__(256)
void softmax_apply(const float* __restrict__ S,
                   const float* __restrict__ rmax, const float* __restrict__ rinv,
                   const float* __restrict__ cmax, const float* __restrict__ cinv,
                   __nv_bfloat16* __restrict__ A1h, __nv_bfloat16* __restrict__ A1l,
                   __nv_bfloat16* __restrict__ A2h, __nv_bfloat16* __restrict__ A2l)
{
    __shared__ float tle[32][33];
    const int z = blockIdx.z;
    const int bx = blockIdx.x * 32, by = blockIdx.y * 32;
    const int x = threadIdx.x, y = threadIdx.y;
    const float* Sp = S + (size_t)z * MATS;
#pragma unroll
    for (int i = 0; i < 4; i++) {
        int row = by + y + 8 * i;
        float v = Sp[(size_t)row * DIMN + bx + x];
        tle[y + 8 * i][x] = v;
        float val = __expf(v - rmax[z * DIMN + row]) * rinv[z * DIMN + row];
        __nv_bfloat16 hh, ll;
        bsplit(val, hh, ll);
        size_t o = (size_t)z * MATS + (size_t)row * DIMN + bx + x;
        A1h[o] = hh; A1l[o] = ll;
    }
    __syncthreads();
#pragma unroll
    for (int i = 0; i < 4; i++) {
        int cI = bx + y + 8 * i;
        float v = tle[x][y + 8 * i];
        float val = __expf(v - cmax[z * DIMN + cI]) * cinv[z * DIMN + cI];
        __nv_bfloat16 hh, ll;
        bsplit(val, hh, ll);
        size_t o = (size_t)z * MATS + (size_t)cI * DIMN + by + x;
        A2h[o] = hh; A2l[o] = ll;
    }
}

// ---------------- launcher ----------------
extern "C" void kernel_launch(void* const* d_in, const int* in_sizes, int n_in,
                              void* d_out, int out_size)
{
    const float* a1 = (const float*)d_in[0];
    const float* a2 = (const float*)d_in[1];
    const float* Gw = (const float*)d_in[2];
    const float* Gb = (const float*)d_in[3];
    float* M1 = (float*)d_out;
    float* M2 = M1 + TOT;

    __nv_bfloat16 *a1h, *a1l, *a2h, *a2l, *gwh, *gwl, *a2ph, *a2pl;
    __nv_bfloat16 *A1h, *A1l, *A2h, *A2l, *a2Th, *a2Tl, *a1Th, *a1Tl;
    float *S, *rmax, *rinv, *cmax, *cinv, *rpm, *rps, *cpm, *cps;
    cudaGetSymbolAddress((void**)&a1h, g_a1h);   cudaGetSymbolAddress((void**)&a1l, g_a1l);
    cudaGetSymbolAddress((void**)&a2h, g_a2h);   cudaGetSymbolAddress((void**)&a2l, g_a2l);
    cudaGetSymbolAddress((void**)&gwh, g_gwh);   cudaGetSymbolAddress((void**)&gwl, g_gwl);
    cudaGetSymbolAddress((void**)&a2ph, g_a2ph); cudaGetSymbolAddress((void**)&a2pl, g_a2pl);
    cudaGetSymbolAddress((void**)&A1h, g_A1h);   cudaGetSymbolAddress((void**)&A1l, g_A1l);
    cudaGetSymbolAddress((void**)&A2h, g_A2h);   cudaGetSymbolAddress((void**)&A2l, g_A2l);
    cudaGetSymbolAddress((void**)&a2Th, g_a2Th); cudaGetSymbolAddress((void**)&a2Tl, g_a2Tl);
    cudaGetSymbolAddress((void**)&a1Th, g_a1Th); cudaGetSymbolAddress((void**)&a1Tl, g_a1Tl);
    cudaGetSymbolAddress((void**)&S, g_S);
    cudaGetSymbolAddress((void**)&rmax, g_rmax); cudaGetSymbolAddress((void**)&rinv, g_rinv);
    cudaGetSymbolAddress((void**)&cmax, g_cmax); cudaGetSymbolAddress((void**)&cinv, g_cinv);
    cudaGetSymbolAddress((void**)&rpm, g_rpm);   cudaGetSymbolAddress((void**)&rps, g_rps);
    cudaGetSymbolAddress((void**)&cpm, g_cpm);   cudaGetSymbolAddress((void**)&cps, g_cps);

    cudaFuncSetAttribute(gemm_a2p,  cudaFuncAttributeMaxDynamicSharedMemorySize, SMEM_TOT);
    cudaFuncSetAttribute(gemm_S,    cudaFuncAttributeMaxDynamicSharedMemorySize, SMEM_TOT);
    cudaFuncSetAttribute(gemm_dual, cudaFuncAttributeMaxDynamicSharedMemorySize, SMEM_TOT);

    // fused splits: row-major + transposed in one pass
    fsplit_kernel<<<dim3(32, 32, NB), dim3(32, 8)>>>(a1, a1h, a1l, a1Th, a1Tl);
    fsplit_kernel<<<dim3(32, 32, NB), dim3(32, 8)>>>(a2, a2h, a2l, a2Th, a2Tl);
    split_kernel<<<1024, 256>>>(Gw, gwh, gwl);

    // 1) a2p = a2 @ Gw^T + Gb  -> split bf16 pair
    gemm_a2p<<<dim3(4, 128, 1), 256, SMEM_TOT>>>(a2h, a2l, gwh, gwl, a2ph, a2pl, Gb);

    // 2) S[n] = a1[n] @ a2p[n]^T + fused softmax partials
    gemm_S<<<dim3(4, 8, NB), 256, SMEM_TOT>>>(a1h, a1l, a2ph, a2pl, S, rpm, rps, cpm, cps);

    // 3) combine partials -> (max, 1/sum)
    combine_kernel<4><<<64, 256>>>(rpm, rps, rmax, rinv);
    combine_kernel<8><<<64, 256>>>(cpm, cps, cmax, cinv);

    // 4) fused softmax apply: A1 (row-major) + A2^T
    softmax_apply<<<dim3(32, 32, NB), dim3(32, 8)>>>(
        S, rmax, rinv, cmax, cinv, A1h, A1l, A2h, A2l);

    // 5) M1 = A1 @ a2  and  M2 = A2^T @ a1 in one launch
    gemm_dual<<<dim3(4, 8, 2 * NB), 256, SMEM_TOT>>>(
        A1h, A1l, a2Th, a2Tl, M1,
        A2h, A2l, a1Th, a1Tl, M2);
}